// round 3
// baseline (speedup 1.0000x reference)
#include <cuda_runtime.h>

// Problem constants (fixed shapes from the reference)
#define NE      513              // NUM_EDGES + 1
#define LHOPS   5
#define HEADS   8
#define FEAT    64
#define NPAIRS  (8*128*128)      // 131072
#define PROJ_ELEMS (LHOPS*NE*HEADS)   // 20520 floats = 82080 B
#define CHUNK   886              // ceil(NPAIRS / 148)

// Precomputed projection table proj[l][e][h]
__device__ __align__(16) float g_proj[PROJ_ELEMS];

// Kernel A (tiled mini-GEMM): proj[l][e][h] = sum_f edge_emb[e][f]*attn_w[l][f][h]
// grid = (17 e-tiles, 5 l), block = 256 = 32 e x 8 h. w[l] staged in smem.
__global__ void proj_kernel(const float* __restrict__ emb,
                            const float* __restrict__ w) {
    __shared__ __align__(16) float s_w[FEAT * HEADS];   // 2 KB
    const int l   = blockIdx.y;
    const int tid = threadIdx.x;
    for (int i = tid; i < FEAT * HEADS / 4; i += 256)
        ((float4*)s_w)[i] = ((const float4*)(w + l * FEAT * HEADS))[i];
    __syncthreads();

    const int e = blockIdx.x * 32 + (tid >> 3);
    const int h = tid & 7;
    if (e >= NE) return;
    const float* er = emb + e * FEAT;
    float acc = 0.f;
    #pragma unroll
    for (int f = 0; f < FEAT; ++f)
        acc = fmaf(er[f], s_w[f * HEADS + h], acc);  // s_w read: 8-word broadcast, conflict-free
    g_proj[(l * NE + e) * HEADS + h] = acc;          // contiguous per block
}

// Kernel B: 148 CTAs (1/SM) x 512 threads, full 82 KB table in dynamic smem.
// Each thread handles 2 pairs; pd/dist loads are issued BEFORE the staging
// loop so their DRAM latency overlaps table staging.
__global__ void __launch_bounds__(512)
enc_kernel(const void* __restrict__ distp,
           const void* __restrict__ pdp,
           float* __restrict__ out) {
    extern __shared__ float s_proj[];   // 82080 B
    const int tid  = threadIdx.x;
    const int base = blockIdx.x * CHUNK;

    // dtype detection: dist in [1,5]; int64 (LE) => word #1 is high half == 0.
    const bool is64 = (((const int*)distp)[1] == 0);

    const int p0r = base + tid;
    const int p1r = base + 512 + tid;
    const bool v0 = (tid < CHUNK) && (p0r < NPAIRS);
    const bool v1 = (512 + tid < CHUNK) && (p1r < NPAIRS);
    const int p0 = v0 ? p0r : base;     // clamp so loads are unconditional
    const int p1 = v1 ? p1r : base;

    // ---- Phase 0: issue all pd + dist loads (overlap with staging) ----
    int idx0[10], idx1[10];
    float sc0, sc1;
    if (is64) {
        const int* pd = (const int*)pdp;      // low words at stride 2
        #pragma unroll
        for (int j = 0; j < 10; ++j) idx0[j] = pd[(size_t)p0 * 20 + 2 * j];
        #pragma unroll
        for (int j = 0; j < 10; ++j) idx1[j] = pd[(size_t)p1 * 20 + 2 * j];
        sc0 = 0.5f / (float)((const int*)distp)[2 * p0];   // low word
        sc1 = 0.5f / (float)((const int*)distp)[2 * p1];
    } else {
        const int* pd = (const int*)pdp;
        #pragma unroll
        for (int j = 0; j < 10; ++j) idx0[j] = pd[(size_t)p0 * 10 + j];
        #pragma unroll
        for (int j = 0; j < 10; ++j) idx1[j] = pd[(size_t)p1 * 10 + j];
        sc0 = 0.5f / (float)((const int*)distp)[p0];
        sc1 = 0.5f / (float)((const int*)distp)[p1];
    }

    // ---- Phase 1: cooperative table staging (5130 float4) ----
    {
        const float4* gsrc = (const float4*)g_proj;
        float4* sdst = (float4*)s_proj;
        for (int i = tid; i < PROJ_ELEMS / 4; i += 512)
            sdst[i] = gsrc[i];
    }
    __syncthreads();

    // ---- Phase 2: gathers, two independent accumulator chains ----
    float4 a0l = make_float4(0.f, 0.f, 0.f, 0.f), a0h = a0l;
    float4 a1l = a0l, a1h = a0l;
    #pragma unroll
    for (int j = 0; j < 10; ++j) {
        const int l = j >> 1;             // path_data layout [...,L,D]
        const float4* r0 = (const float4*)(s_proj + (l * NE + idx0[j]) * HEADS);
        const float4* r1 = (const float4*)(s_proj + (l * NE + idx1[j]) * HEADS);
        float4 x0 = r0[0], y0 = r0[1];
        float4 x1 = r1[0], y1 = r1[1];
        a0l.x += x0.x; a0l.y += x0.y; a0l.z += x0.z; a0l.w += x0.w;
        a0h.x += y0.x; a0h.y += y0.y; a0h.z += y0.z; a0h.w += y0.w;
        a1l.x += x1.x; a1l.y += x1.y; a1l.z += x1.z; a1l.w += x1.w;
        a1h.x += y1.x; a1h.y += y1.y; a1h.z += y1.z; a1h.w += y1.w;
    }

    if (v0) {
        float4* o = (float4*)(out + (size_t)p0 * HEADS);
        o[0] = make_float4(a0l.x * sc0, a0l.y * sc0, a0l.z * sc0, a0l.w * sc0);
        o[1] = make_float4(a0h.x * sc0, a0h.y * sc0, a0h.z * sc0, a0h.w * sc0);
    }
    if (v1) {
        float4* o = (float4*)(out + (size_t)p1 * HEADS);
        o[0] = make_float4(a1l.x * sc1, a1l.y * sc1, a1l.z * sc1, a1l.w * sc1);
        o[1] = make_float4(a1h.x * sc1, a1h.y * sc1, a1h.z * sc1, a1h.w * sc1);
    }
}

extern "C" void kernel_launch(void* const* d_in, const int* in_sizes, int n_in,
                              void* d_out, int out_size) {
    const void*  dist = d_in[0];
    const void*  pd   = d_in[1];
    const float* emb  = (const float*)d_in[2];
    const float* w    = (const float*)d_in[3];

    // 82 KB dynamic smem opt-in (idempotent, unconditional)
    cudaFuncSetAttribute(enc_kernel,
                         cudaFuncAttributeMaxDynamicSharedMemorySize,
                         PROJ_ELEMS * (int)sizeof(float));

    proj_kernel<<<dim3((NE + 31) / 32, LHOPS), 256>>>(emb, w);
    enc_kernel<<<148, 512, PROJ_ELEMS * (int)sizeof(float)>>>(
        dist, pd, (float*)d_out);
}

// round 4
// speedup vs baseline: 1.3256x; 1.3256x over previous
#include <cuda_runtime.h>
#include <cuda_fp16.h>

// Problem constants (fixed shapes from the reference)
#define NE      513              // NUM_EDGES + 1
#define LHOPS   5
#define HEADS   8
#define FEAT    64
#define NPAIRS  (8*128*128)      // 131072
#define TBL     (LHOPS*NE*HEADS) // 20520 halves = 41040 B
#define GRID    296
#define CHUNK   443              // ceil(NPAIRS / 296)

// Precomputed projection table proj[l][e][h] in fp16
__device__ __align__(16) __half g_proj[TBL];

// Kernel A (tiled mini-GEMM): proj[l][e][h] = sum_f edge_emb[e][f]*attn_w[l][f][h]
// grid = (17 e-tiles, 5 l), block = 256 = 32 e x 8 h. w[l] staged in smem.
__global__ void proj_kernel(const float* __restrict__ emb,
                            const float* __restrict__ w) {
    __shared__ __align__(16) float s_w[FEAT * HEADS];   // 2 KB
    const int l   = blockIdx.y;
    const int tid = threadIdx.x;
    for (int i = tid; i < FEAT * HEADS / 4; i += 256)
        ((float4*)s_w)[i] = ((const float4*)(w + l * FEAT * HEADS))[i];
    __syncthreads();

    const int e = blockIdx.x * 32 + (tid >> 3);
    const int h = tid & 7;
    if (e >= NE) return;
    const float* er = emb + e * FEAT;
    float acc = 0.f;
    #pragma unroll
    for (int f = 0; f < FEAT; ++f)
        acc = fmaf(er[f], s_w[f * HEADS + h], acc);  // broadcast, conflict-free
    g_proj[(l * NE + e) * HEADS + h] = __float2half(acc);  // coalesced 2B/thread
}

// Kernel B: 296 CTAs (2/SM) x 1024 threads. Full fp16 table (41 KB) in static
// smem. One pair per thread; one LDS.128 per (pair,hop) fetches all 8 heads.
//   out[pair][h] = (0.5/dist[pair]) * sum_{l,d} proj[l][pd[pair][l][d]][h]
__global__ void __launch_bounds__(1024, 2)
enc_kernel(const void* __restrict__ distp,
           const void* __restrict__ pdp,
           float* __restrict__ out) {
    __shared__ __align__(16) __half s_tbl[TBL];  // 41040 B static
    const int tid = threadIdx.x;

    // cooperative staging: 41040 B = 2565 x 16B
    {
        const float4* gsrc = (const float4*)g_proj;
        float4* sdst = (float4*)s_tbl;
        #pragma unroll
        for (int r = 0; r < 3; ++r) {
            int i = tid + r * 1024;
            if (i < TBL / 8) sdst[i] = gsrc[i];
        }
    }
    __syncthreads();

    const int pair = blockIdx.x * CHUNK + tid;
    if (tid >= CHUNK || pair >= NPAIRS) return;

    // dtype detection: dist in [1,5]; int64 (LE) => word #1 is high half == 0.
    const bool is64 = (((const int*)distp)[1] == 0);

    int idx[2 * LHOPS];
    float scale;
    if (is64) {
        // 10 int64 = 80 B contiguous, 16B-aligned
        const int4* p = (const int4*)((const long long*)pdp + (size_t)pair * 10);
        #pragma unroll
        for (int j = 0; j < 5; ++j) {
            int4 v = p[j];               // low words of two int64: .x, .z
            idx[2 * j]     = v.x;
            idx[2 * j + 1] = v.z;
        }
        scale = 0.5f / (float)((const int*)distp)[2 * pair];  // low word
    } else {
        // 10 int32 = 40 B contiguous, 8B-aligned
        const int2* p = (const int2*)((const int*)pdp + (size_t)pair * 10);
        #pragma unroll
        for (int j = 0; j < 5; ++j) {
            int2 v = p[j];
            idx[2 * j]     = v.x;
            idx[2 * j + 1] = v.y;
        }
        scale = 0.5f / (float)((const int*)distp)[pair];
    }

    float4 al = make_float4(0.f, 0.f, 0.f, 0.f);
    float4 ah = al;
    #pragma unroll
    for (int j = 0; j < 2 * LHOPS; ++j) {
        const int l = j >> 1;            // path_data layout [...,L,D]
        // one 16B gather = all 8 fp16 heads
        float4 rv = *(const float4*)(s_tbl + (l * NE + idx[j]) * HEADS);
        __half2 h0 = *(__half2*)&rv.x;
        __half2 h1 = *(__half2*)&rv.y;
        __half2 h2 = *(__half2*)&rv.z;
        __half2 h3 = *(__half2*)&rv.w;
        float2 f0 = __half22float2(h0);
        float2 f1 = __half22float2(h1);
        float2 f2 = __half22float2(h2);
        float2 f3 = __half22float2(h3);
        al.x += f0.x; al.y += f0.y; al.z += f1.x; al.w += f1.y;
        ah.x += f2.x; ah.y += f2.y; ah.z += f3.x; ah.w += f3.y;
    }

    float4* o = (float4*)(out + (size_t)pair * HEADS);
    o[0] = make_float4(al.x * scale, al.y * scale, al.z * scale, al.w * scale);
    o[1] = make_float4(ah.x * scale, ah.y * scale, ah.z * scale, ah.w * scale);
}

extern "C" void kernel_launch(void* const* d_in, const int* in_sizes, int n_in,
                              void* d_out, int out_size) {
    const void*  dist = d_in[0];
    const void*  pd   = d_in[1];
    const float* emb  = (const float*)d_in[2];
    const float* w    = (const float*)d_in[3];

    proj_kernel<<<dim3((NE + 31) / 32, LHOPS), 256>>>(emb, w);
    enc_kernel<<<GRID, 1024>>>(dist, pd, (float*)d_out);
}